// round 1
// baseline (speedup 1.0000x reference)
#include <cuda_runtime.h>
#include <cstdint>

// Problem constants
#define TT   4096          // B*T tokens
#define DD   2048          // model dim
#define FF   2048          // hidden dim
#define EE   8             // experts
#define CAP  4096          // per-expert capacity (worst case)
#define N13  (2*FF)        // 4096

// ---------------- scratch (device globals; no runtime allocation) -------------
__device__ float g_h_shared[(size_t)TT * N13];          //  67 MB
__device__ float g_act_shared[(size_t)TT * FF];         //  33 MB
__device__ float g_h_routed[(size_t)EE * CAP * N13];    // 537 MB
__device__ float g_act_routed[(size_t)EE * CAP * FF];   // 268 MB
__device__ float g_z_routed[(size_t)EE * CAP * DD];     // 268 MB
__device__ int   g_counts[EE];
__device__ int   g_tok[EE * CAP];
__device__ float g_gate[EE * CAP];
__device__ int   g_slot[2 * TT];

// ---------------- init ----------------
__global__ void init_kernel() {
    if (threadIdx.x < EE) g_counts[threadIdx.x] = 0;
}

// ---------------- router: sigmoid scores + top-2 scatter ----------------
__global__ void router_kernel(const float* __restrict__ x,
                              const float* __restrict__ router)
{
    int warp = (blockIdx.x * blockDim.x + threadIdx.x) >> 5;
    int lane = threadIdx.x & 31;
    if (warp >= TT) return;
    const float* xt = x + (size_t)warp * DD;
    float s[EE];
#pragma unroll
    for (int e = 0; e < EE; e++) s[e] = 0.f;
    for (int d = lane; d < DD; d += 32) {
        float xv = xt[d];
        const float* rr = router + (size_t)d * EE;
#pragma unroll
        for (int e = 0; e < EE; e++) s[e] += xv * rr[e];
    }
#pragma unroll
    for (int e = 0; e < EE; e++) {
#pragma unroll
        for (int off = 16; off; off >>= 1)
            s[e] += __shfl_xor_sync(0xffffffffu, s[e], off);
    }
    if (lane == 0) {
        float sc[EE];
#pragma unroll
        for (int e = 0; e < EE; e++) sc[e] = 1.f / (1.f + expf(-s[e]));
        int i1 = 0;
#pragma unroll
        for (int e = 1; e < EE; e++) if (sc[e] > sc[i1]) i1 = e;
        int i2 = (i1 == 0) ? 1 : 0;
#pragma unroll
        for (int e = 0; e < EE; e++)
            if (e != i1 && sc[e] > sc[i2]) i2 = e;

        int p1 = atomicAdd(&g_counts[i1], 1);
        g_tok[i1 * CAP + p1]  = warp;
        g_gate[i1 * CAP + p1] = sc[i1];
        g_slot[2 * warp]      = i1 * CAP + p1;

        int p2 = atomicAdd(&g_counts[i2], 1);
        g_tok[i2 * CAP + p2]  = warp;
        g_gate[i2 * CAP + p2] = sc[i2];
        g_slot[2 * warp + 1]  = i2 * CAP + p2;
    }
}

// ---------------- generic tiled SGEMM:  C = A @ B^T  ----------------
// A: M x K rows (optionally gathered via tok_list per expert), B: N x K (row-major,
// per-expert stride N*K), C: M x N (row base = e*cap). counts==nullptr -> plain.
#define BM 128
#define BN 128
#define BK 16

__global__ void __launch_bounds__(256, 2) gemm_kernel(
    const float* __restrict__ A, const float* __restrict__ B, float* __restrict__ C,
    int M, int N, int K,
    const int* __restrict__ counts, const int* __restrict__ tok_list, int cap)
{
    const int e   = blockIdx.z;
    const int cnt = counts ? counts[e] : M;
    const int m0  = blockIdx.y * BM;
    if (m0 >= cnt) return;
    const int n0  = blockIdx.x * BN;
    const size_t rowbase = (size_t)e * cap;

    __shared__ float As[2][BK][BM];
    __shared__ float Bs[2][BK][BN];

    const int tid = threadIdx.x;
    const int ar  = tid >> 2;          // 0..63
    const int ac  = (tid & 3) << 2;    // 0,4,8,12

    const float* pA0;
    const float* pA1;
    if (tok_list) {
        int r0 = m0 + ar, r1 = m0 + ar + 64;
        int t0 = (r0 < cnt) ? tok_list[rowbase + r0] : 0;
        int t1 = (r1 < cnt) ? tok_list[rowbase + r1] : 0;
        pA0 = A + (size_t)t0 * K + ac;
        pA1 = A + (size_t)t1 * K + ac;
    } else {
        pA0 = A + (rowbase + m0 + ar) * (size_t)K + ac;
        pA1 = pA0 + (size_t)64 * K;
    }
    const float* pB0 = B + (size_t)e * N * K + (size_t)(n0 + ar) * K + ac;
    const float* pB1 = pB0 + (size_t)64 * K;

    float4 la0 = *(const float4*)pA0;
    float4 la1 = *(const float4*)pA1;
    float4 lb0 = *(const float4*)pB0;
    float4 lb1 = *(const float4*)pB1;

    int buf = 0;
#pragma unroll
    for (int i = 0; i < 4; ++i) {
        As[0][ac + i][ar]      = ((const float*)&la0)[i];
        As[0][ac + i][ar + 64] = ((const float*)&la1)[i];
        Bs[0][ac + i][ar]      = ((const float*)&lb0)[i];
        Bs[0][ac + i][ar + 64] = ((const float*)&lb1)[i];
    }
    __syncthreads();

    float acc[8][8];
#pragma unroll
    for (int i = 0; i < 8; i++)
#pragma unroll
        for (int j = 0; j < 8; j++) acc[i][j] = 0.f;

    const int ty = tid >> 4, tx = tid & 15;
    const int ntiles = K / BK;

    for (int t = 0; t < ntiles; ++t) {
        if (t + 1 < ntiles) {
            int ko = (t + 1) * BK;
            la0 = *(const float4*)(pA0 + ko);
            la1 = *(const float4*)(pA1 + ko);
            lb0 = *(const float4*)(pB0 + ko);
            lb1 = *(const float4*)(pB1 + ko);
        }
#pragma unroll
        for (int kk = 0; kk < BK; ++kk) {
            float4 a0 = *(const float4*)&As[buf][kk][ty * 4];
            float4 a1 = *(const float4*)&As[buf][kk][ty * 4 + 64];
            float4 b0 = *(const float4*)&Bs[buf][kk][tx * 4];
            float4 b1 = *(const float4*)&Bs[buf][kk][tx * 4 + 64];
            float av[8] = {a0.x, a0.y, a0.z, a0.w, a1.x, a1.y, a1.z, a1.w};
            float bv[8] = {b0.x, b0.y, b0.z, b0.w, b1.x, b1.y, b1.z, b1.w};
#pragma unroll
            for (int i = 0; i < 8; i++)
#pragma unroll
                for (int j = 0; j < 8; j++)
                    acc[i][j] += av[i] * bv[j];
        }
        if (t + 1 < ntiles) {
            buf ^= 1;
#pragma unroll
            for (int i = 0; i < 4; ++i) {
                As[buf][ac + i][ar]      = ((const float*)&la0)[i];
                As[buf][ac + i][ar + 64] = ((const float*)&la1)[i];
                Bs[buf][ac + i][ar]      = ((const float*)&lb0)[i];
                Bs[buf][ac + i][ar + 64] = ((const float*)&lb1)[i];
            }
            __syncthreads();
        }
    }

#pragma unroll
    for (int i = 0; i < 8; ++i) {
        int rr = (i < 4) ? (ty * 4 + i) : (64 + ty * 4 + i - 4);
        int r  = m0 + rr;
        if (r < cnt) {
            float* cp = C + (rowbase + r) * (size_t)N + n0;
            float4 v0 = make_float4(acc[i][0], acc[i][1], acc[i][2], acc[i][3]);
            float4 v1 = make_float4(acc[i][4], acc[i][5], acc[i][6], acc[i][7]);
            *(float4*)(cp + tx * 4)      = v0;
            *(float4*)(cp + 64 + tx * 4) = v1;
        }
    }
}

// ---------------- swiglu epilogues ----------------
__global__ void swiglu_shared_kernel()
{
    int t = blockIdx.x;
    const float* h = g_h_shared + (size_t)t * N13;
    float* a = g_act_shared + (size_t)t * FF;
    for (int f = threadIdx.x; f < FF; f += blockDim.x) {
        float y0 = h[f], y1 = h[FF + f];
        a[f] = y0 * (1.f / (1.f + expf(-y0))) * y1;
    }
}

__global__ void swiglu_routed_kernel()
{
    int e   = blockIdx.y;
    int pos = blockIdx.x;
    if (pos >= g_counts[e]) return;
    size_t s = (size_t)e * CAP + pos;
    float g = g_gate[s];
    const float* h = g_h_routed + s * N13;
    float* a = g_act_routed + s * FF;
    for (int f = threadIdx.x; f < FF; f += blockDim.x) {
        float y0 = g * h[f], y1 = g * h[FF + f];
        a[f] = y0 * (1.f / (1.f + expf(-y0))) * y1;
    }
}

// ---------------- final combine: out = shared_z (already in out) + z_e1 + z_e2 --
__global__ void final_add_kernel(float* __restrict__ out)
{
    int t = blockIdx.x;
    size_t s0 = (size_t)g_slot[2 * t];
    size_t s1 = (size_t)g_slot[2 * t + 1];
    float* o = out + (size_t)t * DD;
    const float* z0 = g_z_routed + s0 * DD;
    const float* z1 = g_z_routed + s1 * DD;
    for (int d = threadIdx.x; d < DD; d += blockDim.x)
        o[d] += z0[d] + z1[d];
}

// ---------------- launch ----------------
extern "C" void kernel_launch(void* const* d_in, const int* in_sizes, int n_in,
                              void* d_out, int out_size)
{
    const float* x    = (const float*)d_in[0];
    const float* rte  = (const float*)d_in[1];
    const float* sw13 = (const float*)d_in[2];
    const float* sw2  = (const float*)d_in[3];
    const float* rw13 = (const float*)d_in[4];
    const float* rw2  = (const float*)d_in[5];
    float* out = (float*)d_out;

    float *h_sh, *a_sh, *h_rt, *a_rt, *z_rt;
    int *cnts, *toks;
    cudaGetSymbolAddress((void**)&h_sh, g_h_shared);
    cudaGetSymbolAddress((void**)&a_sh, g_act_shared);
    cudaGetSymbolAddress((void**)&h_rt, g_h_routed);
    cudaGetSymbolAddress((void**)&a_rt, g_act_routed);
    cudaGetSymbolAddress((void**)&z_rt, g_z_routed);
    cudaGetSymbolAddress((void**)&cnts, g_counts);
    cudaGetSymbolAddress((void**)&toks, g_tok);

    init_kernel<<<1, 32>>>();
    router_kernel<<<TT / 8, 256>>>(x, rte);

    // shared expert
    gemm_kernel<<<dim3(N13 / BN, TT / BM, 1), 256>>>(x, sw13, h_sh, TT, N13, DD,
                                                     nullptr, nullptr, 0);
    swiglu_shared_kernel<<<TT, 256>>>();
    gemm_kernel<<<dim3(DD / BN, TT / BM, 1), 256>>>(a_sh, sw2, out, TT, DD, FF,
                                                    nullptr, nullptr, 0);

    // routed experts (grouped, count-guarded)
    gemm_kernel<<<dim3(N13 / BN, CAP / BM, EE), 256>>>(x, rw13, h_rt, CAP, N13, DD,
                                                       cnts, toks, CAP);
    swiglu_routed_kernel<<<dim3(CAP, EE), 256>>>();
    gemm_kernel<<<dim3(DD / BN, CAP / BM, EE), 256>>>(a_rt, rw2, z_rt, CAP, DD, FF,
                                                      cnts, nullptr, CAP);

    final_add_kernel<<<TT, 256>>>(out);
}

// round 3
// speedup vs baseline: 1.7067x; 1.7067x over previous
#include <cuda_runtime.h>
#include <cuda_bf16.h>
#include <cstdint>

#define TT   4096
#define DD   2048
#define FF   2048
#define EE   8
#define CAP  4096

// ---------------- bf16 hi/lo split storage ----------------
__device__ __nv_bfloat16 g_x_hi[(size_t)TT * DD];
__device__ __nv_bfloat16 g_x_lo[(size_t)TT * DD];
__device__ __nv_bfloat16 g_sw13_hi[(size_t)2 * FF * DD];
__device__ __nv_bfloat16 g_sw13_lo[(size_t)2 * FF * DD];
__device__ __nv_bfloat16 g_sw2_hi[(size_t)DD * FF];
__device__ __nv_bfloat16 g_sw2_lo[(size_t)DD * FF];
__device__ __nv_bfloat16 g_rw13_hi[(size_t)EE * 2 * FF * DD];
__device__ __nv_bfloat16 g_rw13_lo[(size_t)EE * 2 * FF * DD];
__device__ __nv_bfloat16 g_rw2_hi[(size_t)EE * DD * FF];
__device__ __nv_bfloat16 g_rw2_lo[(size_t)EE * DD * FF];
__device__ __nv_bfloat16 g_actsh_hi[(size_t)TT * FF];
__device__ __nv_bfloat16 g_actsh_lo[(size_t)TT * FF];
__device__ __nv_bfloat16 g_actrt_hi[(size_t)EE * CAP * FF];
__device__ __nv_bfloat16 g_actrt_lo[(size_t)EE * CAP * FF];
__device__ float g_z[(size_t)EE * CAP * DD];
__device__ int   g_counts[EE];
__device__ int   g_tok[EE * CAP];
__device__ float g_gate[EE * CAP];
__device__ int   g_slot[2 * TT];

// ---------------- PTX helpers (baseline sm_80/90 features only) -------------
__device__ __forceinline__ uint32_t smem_u32(const void* p) {
    uint32_t a;
    asm("{ .reg .u64 t; cvta.to.shared.u64 t, %1; cvt.u32.u64 %0, t; }" : "=r"(a) : "l"(p));
    return a;
}
#define CPA16(d, s) \
    asm volatile("cp.async.cg.shared.global [%0], [%1], 16;" :: "r"(d), "l"(s) : "memory")
#define CPA_COMMIT() asm volatile("cp.async.commit_group;" ::: "memory")
#define CPA_WAIT2()  asm volatile("cp.async.wait_group 2;" ::: "memory")

#define LDSM4(r0, r1, r2, r3, addr) \
    asm volatile("ldmatrix.sync.aligned.m8n8.x4.shared.b16 {%0,%1,%2,%3}, [%4];" \
                 : "=r"(r0), "=r"(r1), "=r"(r2), "=r"(r3) : "r"(addr))
#define LDSM2(r0, r1, addr) \
    asm volatile("ldmatrix.sync.aligned.m8n8.x2.shared.b16 {%0,%1}, [%2];" \
                 : "=r"(r0), "=r"(r1) : "r"(addr))

#define MMA16816(d, a, b) \
    asm volatile("mma.sync.aligned.m16n8k16.row.col.f32.bf16.bf16.f32 " \
                 "{%0,%1,%2,%3}, {%4,%5,%6,%7}, {%8,%9}, {%0,%1,%2,%3};" \
                 : "+f"((d)[0]), "+f"((d)[1]), "+f"((d)[2]), "+f"((d)[3]) \
                 : "r"((a)[0]), "r"((a)[1]), "r"((a)[2]), "r"((a)[3]), \
                   "r"((b)[0]), "r"((b)[1]))

// smem: [tok 512][gate 512][3 stages x 20480 : A 10240 | B 10240]
#define STAGE_SZ   20480
#define SM_STAGES  1024
#define SMEM_BYTES (SM_STAGES + 3 * STAGE_SZ)   // 62464

// ---------------- misc kernels ----------------
__global__ void init_kernel() {
    if (threadIdx.x < EE) g_counts[threadIdx.x] = 0;
}

__global__ void split_kernel(const float4* __restrict__ in,
                             __nv_bfloat162* __restrict__ hi,
                             __nv_bfloat162* __restrict__ lo, int n4)
{
    int i = blockIdx.x * blockDim.x + threadIdx.x;
    if (i >= n4) return;
    float4 v = in[i];
    __nv_bfloat16 h0 = __float2bfloat16(v.x), h1 = __float2bfloat16(v.y);
    __nv_bfloat16 h2 = __float2bfloat16(v.z), h3 = __float2bfloat16(v.w);
    __nv_bfloat16 l0 = __float2bfloat16(v.x - __bfloat162float(h0));
    __nv_bfloat16 l1 = __float2bfloat16(v.y - __bfloat162float(h1));
    __nv_bfloat16 l2 = __float2bfloat16(v.z - __bfloat162float(h2));
    __nv_bfloat16 l3 = __float2bfloat16(v.w - __bfloat162float(h3));
    hi[2 * i]     = __halves2bfloat162(h0, h1);
    hi[2 * i + 1] = __halves2bfloat162(h2, h3);
    lo[2 * i]     = __halves2bfloat162(l0, l1);
    lo[2 * i + 1] = __halves2bfloat162(l2, l3);
}

__global__ void router_kernel(const float* __restrict__ x,
                              const float* __restrict__ router)
{
    int warp = (blockIdx.x * blockDim.x + threadIdx.x) >> 5;
    int lane = threadIdx.x & 31;
    if (warp >= TT) return;
    const float* xt = x + (size_t)warp * DD;
    float s[EE];
#pragma unroll
    for (int e = 0; e < EE; e++) s[e] = 0.f;
    for (int d = lane; d < DD; d += 32) {
        float xv = xt[d];
        const float* rr = router + (size_t)d * EE;
#pragma unroll
        for (int e = 0; e < EE; e++) s[e] += xv * rr[e];
    }
#pragma unroll
    for (int e = 0; e < EE; e++)
#pragma unroll
        for (int off = 16; off; off >>= 1)
            s[e] += __shfl_xor_sync(0xffffffffu, s[e], off);
    if (lane == 0) {
        float sc[EE];
#pragma unroll
        for (int e = 0; e < EE; e++) sc[e] = 1.f / (1.f + expf(-s[e]));
        int i1 = 0;
#pragma unroll
        for (int e = 1; e < EE; e++) if (sc[e] > sc[i1]) i1 = e;
        int i2 = (i1 == 0) ? 1 : 0;
#pragma unroll
        for (int e = 0; e < EE; e++)
            if (e != i1 && sc[e] > sc[i2]) i2 = e;
        int p1 = atomicAdd(&g_counts[i1], 1);
        g_tok[i1 * CAP + p1]  = warp;
        g_gate[i1 * CAP + p1] = sc[i1];
        g_slot[2 * warp]      = i1 * CAP + p1;
        int p2 = atomicAdd(&g_counts[i2], 1);
        g_tok[i2 * CAP + p2]  = warp;
        g_gate[i2 * CAP + p2] = sc[i2];
        g_slot[2 * warp + 1]  = i2 * CAP + p2;
    }
}

__global__ void final_add_kernel(float* __restrict__ out)
{
    int t = blockIdx.x;
    size_t s0 = (size_t)g_slot[2 * t];
    size_t s1 = (size_t)g_slot[2 * t + 1];
    float* o = out + (size_t)t * DD;
    const float* z0 = g_z + s0 * DD;
    const float* z1 = g_z + s1 * DD;
    for (int d = threadIdx.x; d < DD; d += blockDim.x)
        o[d] += z0[d] + z1[d];
}

// ---------------- HMMA GEMM: C = A @ B^T over K=2048, bf16x3 compensated ----
// CTA tile 128x128, 8 warps (2x4), warp tile 64x32, mma m16n8k16, BK=32,
// 3-stage cp.async ring. IS13: B rows interleave w1(even)/w3(odd) so each
// thread's (d0,d1) pair is (y0,y1) of one act column -> fused gate+SwiGLU.
template<bool IS13, bool GATHER>
__global__ void __launch_bounds__(256, 2) moe_gemm(
    const __nv_bfloat16* __restrict__ a_hi, const __nv_bfloat16* __restrict__ a_lo,
    const __nv_bfloat16* __restrict__ b_hi, const __nv_bfloat16* __restrict__ b_lo,
    __nv_bfloat16* __restrict__ out_hi, __nv_bfloat16* __restrict__ out_lo,
    float* __restrict__ out_f,
    int Mfull, const int* __restrict__ counts,
    const int* __restrict__ tok, const float* __restrict__ gate,
    size_t b_estride, int acap, int ccap)
{
    extern __shared__ char smem[];
    const int e   = blockIdx.z;
    const int cnt = counts ? counts[e] : Mfull;
    const int m0  = blockIdx.y * 128;
    if (m0 >= cnt) return;
    const int tid = threadIdx.x;
    const int lane = tid & 31, wid = tid >> 5;

    int*   tok_s  = (int*)smem;
    float* gate_s = (float*)(smem + 512);
    if (GATHER && tid < 128) {
        int r = m0 + tid;
        tok_s[tid]  = (r < cnt) ? tok[e * CAP + r]  : 0;
        gate_s[tid] = (r < cnt) ? gate[e * CAP + r] : 0.f;
    }
    __syncthreads();

    const uint32_t sb = smem_u32(smem) + SM_STAGES;

    // ---- cp.async addressing: thread -> (row = tid/2, 32B half of 64B k-chunk)
    const int lr = tid >> 1;
    const int lc = (tid & 1) * 32;
    size_t aRow;
    if (GATHER) aRow = (size_t)tok_s[lr];
    else        aRow = (size_t)e * (size_t)acap + (size_t)(m0 + lr);
    const char* pAhi = (const char*)(a_hi + aRow * 2048) + lc;
    const char* pAlo = (const char*)(a_lo + aRow * 2048) + lc;
    size_t bRow;
    if (IS13) bRow = (size_t)((lr & 1) * 2048 + blockIdx.x * 64 + (lr >> 1));
    else      bRow = (size_t)(blockIdx.x * 128 + lr);
    const char* pBhi = (const char*)(b_hi + (size_t)e * b_estride + bRow * 2048) + lc;
    const char* pBlo = (const char*)(b_lo + (size_t)e * b_estride + bRow * 2048) + lc;
    const uint32_t dA = (uint32_t)(lr * 80 + lc);
    const uint32_t dB = (uint32_t)(10240 + lr * 80 + lc);

    // ---- ldmatrix offsets (relative to stage base); padded stride 80B rows
    const int mw = wid >> 2, nw = wid & 3;
    uint32_t aoff[4], boff[4];
#pragma unroll
    for (int mi = 0; mi < 4; mi++)
        aoff[mi] = (uint32_t)((mw * 64 + mi * 16 + (lane & 15)) * 80 + (lane >> 4) * 16);
#pragma unroll
    for (int nj = 0; nj < 4; nj++)
        boff[nj] = (uint32_t)(10240 + (nw * 32 + nj * 8 + (lane & 7)) * 80 +
                              ((lane >> 3) & 1) * 16);

    float acc[4][4][4];
#pragma unroll
    for (int mi = 0; mi < 4; mi++)
#pragma unroll
        for (int nj = 0; nj < 4; nj++)
#pragma unroll
            for (int q = 0; q < 4; q++) acc[mi][nj][q] = 0.f;

    // iteration c: phase = c/64 (hi*hi, lo*hi, hi*lo), k-chunk = (c%64)*32
    auto issue = [&](int c) {
        const int s  = c % 3;
        const int ph = c >> 6;
        const int kb = (c & 63) * 64;           // bytes
        const char* pa = (ph == 1) ? pAlo : pAhi;
        const char* pb = (ph == 2) ? pBlo : pBhi;
        const uint32_t st = sb + s * STAGE_SZ;
        CPA16(st + dA,      pa + kb);
        CPA16(st + dA + 16, pa + kb + 16);
        CPA16(st + dB,      pb + kb);
        CPA16(st + dB + 16, pb + kb + 16);
    };

    issue(0); CPA_COMMIT();
    issue(1); CPA_COMMIT();
    issue(2); CPA_COMMIT();

    for (int c = 0; c < 192; c++) {
        CPA_WAIT2();
        __syncthreads();
        const uint32_t st = sb + (c % 3) * STAGE_SZ;
#pragma unroll
        for (int ks = 0; ks < 2; ks++) {
            uint32_t a[4][4], b[4][2];
#pragma unroll
            for (int mi = 0; mi < 4; mi++)
                LDSM4(a[mi][0], a[mi][1], a[mi][2], a[mi][3], st + aoff[mi] + ks * 32);
#pragma unroll
            for (int nj = 0; nj < 4; nj++)
                LDSM2(b[nj][0], b[nj][1], st + boff[nj] + ks * 32);
#pragma unroll
            for (int mi = 0; mi < 4; mi++)
#pragma unroll
                for (int nj = 0; nj < 4; nj++)
                    MMA16816(acc[mi][nj], a[mi], b[nj]);
        }
        __syncthreads();
        if (c + 3 < 192) issue(c + 3);
        CPA_COMMIT();
    }

    // ---- epilogue ----
#pragma unroll
    for (int mi = 0; mi < 4; mi++) {
        const int lr0 = mw * 64 + mi * 16 + (lane >> 2);
        const int lr1 = lr0 + 8;
        const int r0 = m0 + lr0, r1 = m0 + lr1;
        float g0 = 1.f, g1 = 1.f;
        if (IS13 && GATHER) { g0 = gate_s[lr0]; g1 = gate_s[lr1]; }
#pragma unroll
        for (int nj = 0; nj < 4; nj++) {
            if (IS13) {
                const int actcol = blockIdx.x * 64 + nw * 16 + nj * 4 + (lane & 3);
                if (r0 < cnt) {
                    float y0 = g0 * acc[mi][nj][0], y1 = g0 * acc[mi][nj][1];
                    float v  = y0 / (1.f + expf(-y0)) * y1;
                    __nv_bfloat16 h = __float2bfloat16(v);
                    size_t o = ((size_t)e * ccap + r0) * 2048 + actcol;
                    out_hi[o] = h;
                    out_lo[o] = __float2bfloat16(v - __bfloat162float(h));
                }
                if (r1 < cnt) {
                    float y0 = g1 * acc[mi][nj][2], y1 = g1 * acc[mi][nj][3];
                    float v  = y0 / (1.f + expf(-y0)) * y1;
                    __nv_bfloat16 h = __float2bfloat16(v);
                    size_t o = ((size_t)e * ccap + r1) * 2048 + actcol;
                    out_hi[o] = h;
                    out_lo[o] = __float2bfloat16(v - __bfloat162float(h));
                }
            } else {
                const int col = blockIdx.x * 128 + nw * 32 + nj * 8 + (lane & 3) * 2;
                if (r0 < cnt)
                    *(float2*)(out_f + ((size_t)e * ccap + r0) * 2048 + col) =
                        make_float2(acc[mi][nj][0], acc[mi][nj][1]);
                if (r1 < cnt)
                    *(float2*)(out_f + ((size_t)e * ccap + r1) * 2048 + col) =
                        make_float2(acc[mi][nj][2], acc[mi][nj][3]);
            }
        }
    }
}

// ---------------- launch ----------------
extern "C" void kernel_launch(void* const* d_in, const int* in_sizes, int n_in,
                              void* d_out, int out_size)
{
    const float* x    = (const float*)d_in[0];
    const float* rte  = (const float*)d_in[1];
    const float* sw13 = (const float*)d_in[2];
    const float* sw2  = (const float*)d_in[3];
    const float* rw13 = (const float*)d_in[4];
    const float* rw2  = (const float*)d_in[5];
    float* out = (float*)d_out;

    __nv_bfloat16 *xh, *xl, *s13h, *s13l, *s2h, *s2l, *r13h, *r13l, *r2h, *r2l;
    __nv_bfloat16 *ash, *asl, *arh, *arl;
    float *z, *gates;
    int *cnts, *toks;
    cudaGetSymbolAddress((void**)&xh, g_x_hi);      cudaGetSymbolAddress((void**)&xl, g_x_lo);
    cudaGetSymbolAddress((void**)&s13h, g_sw13_hi); cudaGetSymbolAddress((void**)&s13l, g_sw13_lo);
    cudaGetSymbolAddress((void**)&s2h, g_sw2_hi);   cudaGetSymbolAddress((void**)&s2l, g_sw2_lo);
    cudaGetSymbolAddress((void**)&r13h, g_rw13_hi); cudaGetSymbolAddress((void**)&r13l, g_rw13_lo);
    cudaGetSymbolAddress((void**)&r2h, g_rw2_hi);   cudaGetSymbolAddress((void**)&r2l, g_rw2_lo);
    cudaGetSymbolAddress((void**)&ash, g_actsh_hi); cudaGetSymbolAddress((void**)&asl, g_actsh_lo);
    cudaGetSymbolAddress((void**)&arh, g_actrt_hi); cudaGetSymbolAddress((void**)&arl, g_actrt_lo);
    cudaGetSymbolAddress((void**)&z, g_z);
    cudaGetSymbolAddress((void**)&cnts, g_counts);
    cudaGetSymbolAddress((void**)&toks, g_tok);
    cudaGetSymbolAddress((void**)&gates, g_gate);

    cudaFuncSetAttribute((const void*)moe_gemm<true,  false>,
                         cudaFuncAttributeMaxDynamicSharedMemorySize, SMEM_BYTES);
    cudaFuncSetAttribute((const void*)moe_gemm<true,  true>,
                         cudaFuncAttributeMaxDynamicSharedMemorySize, SMEM_BYTES);
    cudaFuncSetAttribute((const void*)moe_gemm<false, false>,
                         cudaFuncAttributeMaxDynamicSharedMemorySize, SMEM_BYTES);

    init_kernel<<<1, 32>>>();
    router_kernel<<<TT / 8, 256>>>(x, rte);

    // bf16 hi/lo splits
    {
        struct { const float* in; __nv_bfloat16 *hi, *lo; size_t n; } cv[5] = {
            { x,    xh,   xl,   (size_t)TT * DD },
            { sw13, s13h, s13l, (size_t)2 * FF * DD },
            { sw2,  s2h,  s2l,  (size_t)DD * FF },
            { rw13, r13h, r13l, (size_t)EE * 2 * FF * DD },
            { rw2,  r2h,  r2l,  (size_t)EE * DD * FF },
        };
        for (int i = 0; i < 5; i++) {
            int n4 = (int)(cv[i].n / 4);
            split_kernel<<<(n4 + 255) / 256, 256>>>((const float4*)cv[i].in,
                                                    (__nv_bfloat162*)cv[i].hi,
                                                    (__nv_bfloat162*)cv[i].lo, n4);
        }
    }

    // shared expert GEMM13 (fused swiglu -> act_sh)
    moe_gemm<true, false><<<dim3(FF / 64, TT / 128, 1), 256, SMEM_BYTES>>>(
        xh, xl, s13h, s13l, ash, asl, nullptr,
        TT, nullptr, nullptr, nullptr, 0, TT, TT);

    // routed experts GEMM13 (gathered + gated -> act_rt)
    moe_gemm<true, true><<<dim3(FF / 64, CAP / 128, EE), 256, SMEM_BYTES>>>(
        xh, xl, r13h, r13l, arh, arl, nullptr,
        CAP, cnts, toks, gates, (size_t)2 * FF * DD, 0, CAP);

    // shared GEMM2 -> out (fp32, full overwrite)
    moe_gemm<false, false><<<dim3(DD / 128, TT / 128, 1), 256, SMEM_BYTES>>>(
        ash, asl, s2h, s2l, nullptr, nullptr, out,
        TT, nullptr, nullptr, nullptr, 0, TT, TT);

    // routed GEMM2 -> z
    moe_gemm<false, false><<<dim3(DD / 128, CAP / 128, EE), 256, SMEM_BYTES>>>(
        arh, arl, r2h, r2l, nullptr, nullptr, z,
        CAP, cnts, nullptr, nullptr, (size_t)DD * FF, CAP, CAP);

    final_add_kernel<<<TT, 256>>>(out);
}

// round 4
// speedup vs baseline: 1.7696x; 1.0368x over previous
#include <cuda_runtime.h>
#include <cuda_fp16.h>
#include <cstdint>

#define TT   4096
#define DD   2048
#define FF   2048
#define EE   8
#define CAP  4096

// ---------------- storage: fp16 activations (hi/lo) + fp16 weights ----------
__device__ __half g_x_hi[(size_t)TT * DD];
__device__ __half g_x_lo[(size_t)TT * DD];
__device__ __half g_sw13[(size_t)2 * FF * DD];
__device__ __half g_sw2[(size_t)DD * FF];
__device__ __half g_rw13[(size_t)EE * 2 * FF * DD];
__device__ __half g_rw2[(size_t)EE * DD * FF];
__device__ __half g_actsh_hi[(size_t)TT * FF];
__device__ __half g_actsh_lo[(size_t)TT * FF];
__device__ __half g_actrt_hi[(size_t)EE * CAP * FF];
__device__ __half g_actrt_lo[(size_t)EE * CAP * FF];
__device__ float g_z[(size_t)EE * CAP * DD];
__device__ int   g_counts[EE];
__device__ int   g_tok[EE * CAP];
__device__ float g_gate[EE * CAP];
__device__ int   g_slot[2 * TT];

// ---------------- PTX helpers ----------------
__device__ __forceinline__ uint32_t smem_u32(const void* p) {
    uint32_t a;
    asm("{ .reg .u64 t; cvta.to.shared.u64 t, %1; cvt.u32.u64 %0, t; }" : "=r"(a) : "l"(p));
    return a;
}
#define CPA16(d, s) \
    asm volatile("cp.async.cg.shared.global [%0], [%1], 16;" :: "r"(d), "l"(s) : "memory")
#define CPA_COMMIT() asm volatile("cp.async.commit_group;" ::: "memory")
#define CPA_WAIT1()  asm volatile("cp.async.wait_group 1;" ::: "memory")

#define LDSM4(r0, r1, r2, r3, addr) \
    asm volatile("ldmatrix.sync.aligned.m8n8.x4.shared.b16 {%0,%1,%2,%3}, [%4];" \
                 : "=r"(r0), "=r"(r1), "=r"(r2), "=r"(r3) : "r"(addr))
#define LDSM2(r0, r1, addr) \
    asm volatile("ldmatrix.sync.aligned.m8n8.x2.shared.b16 {%0,%1}, [%2];" \
                 : "=r"(r0), "=r"(r1) : "r"(addr))

#define MMA16816(d, a, b) \
    asm volatile("mma.sync.aligned.m16n8k16.row.col.f32.f16.f16.f32 " \
                 "{%0,%1,%2,%3}, {%4,%5,%6,%7}, {%8,%9}, {%0,%1,%2,%3};" \
                 : "+f"((d)[0]), "+f"((d)[1]), "+f"((d)[2]), "+f"((d)[3]) \
                 : "r"((a)[0]), "r"((a)[1]), "r"((a)[2]), "r"((a)[3]), \
                   "r"((b)[0]), "r"((b)[1]))

// smem: [tok 512][gate 512][3 stages x 32768 : A 16K | B 16K]
#define STAGE_SZ   32768
#define SM_STAGES  1024
#define SMEM_BYTES (SM_STAGES + 3 * STAGE_SZ)   // 99328

// ---------------- fused fp32 -> fp16 conversion (5 tensors, one launch) -----
struct ConvArgs {
    const float4* src[5];
    __half2*      hi[5];
    __half2*      lo[5];     // null for weights
    int           n4[5];
};

__global__ void conv_kernel(ConvArgs a, int total4)
{
    int i = blockIdx.x * blockDim.x + threadIdx.x;
    if (i >= total4) return;
    int r = 0, j = i;
    while (j >= a.n4[r]) { j -= a.n4[r]; r++; }
    float4 v = a.src[r][j];
    __half h0 = __float2half(v.x), h1 = __float2half(v.y);
    __half h2 = __float2half(v.z), h3 = __float2half(v.w);
    a.hi[r][2 * j]     = __halves2half2(h0, h1);
    a.hi[r][2 * j + 1] = __halves2half2(h2, h3);
    if (a.lo[r]) {
        __half l0 = __float2half(v.x - __half2float(h0));
        __half l1 = __float2half(v.y - __half2float(h1));
        __half l2 = __float2half(v.z - __half2float(h2));
        __half l3 = __float2half(v.w - __half2float(h3));
        a.lo[r][2 * j]     = __halves2half2(l0, l1);
        a.lo[r][2 * j + 1] = __halves2half2(l2, l3);
    }
}

// ---------------- misc kernels ----------------
__global__ void init_kernel() {
    if (threadIdx.x < EE) g_counts[threadIdx.x] = 0;
}

__global__ void router_kernel(const float* __restrict__ x,
                              const float* __restrict__ router)
{
    int warp = (blockIdx.x * blockDim.x + threadIdx.x) >> 5;
    int lane = threadIdx.x & 31;
    if (warp >= TT) return;
    const float* xt = x + (size_t)warp * DD;
    float s[EE];
#pragma unroll
    for (int e = 0; e < EE; e++) s[e] = 0.f;
    for (int d = lane; d < DD; d += 32) {
        float xv = xt[d];
        const float* rr = router + (size_t)d * EE;
#pragma unroll
        for (int e = 0; e < EE; e++) s[e] += xv * rr[e];
    }
#pragma unroll
    for (int e = 0; e < EE; e++)
#pragma unroll
        for (int off = 16; off; off >>= 1)
            s[e] += __shfl_xor_sync(0xffffffffu, s[e], off);
    if (lane == 0) {
        float sc[EE];
#pragma unroll
        for (int e = 0; e < EE; e++) sc[e] = 1.f / (1.f + expf(-s[e]));
        int i1 = 0;
#pragma unroll
        for (int e = 1; e < EE; e++) if (sc[e] > sc[i1]) i1 = e;
        int i2 = (i1 == 0) ? 1 : 0;
#pragma unroll
        for (int e = 0; e < EE; e++)
            if (e != i1 && sc[e] > sc[i2]) i2 = e;
        int p1 = atomicAdd(&g_counts[i1], 1);
        g_tok[i1 * CAP + p1]  = warp;
        g_gate[i1 * CAP + p1] = sc[i1];
        g_slot[2 * warp]      = i1 * CAP + p1;
        int p2 = atomicAdd(&g_counts[i2], 1);
        g_tok[i2 * CAP + p2]  = warp;
        g_gate[i2 * CAP + p2] = sc[i2];
        g_slot[2 * warp + 1]  = i2 * CAP + p2;
    }
}

__global__ void final_add_kernel(float* __restrict__ out)
{
    int t = blockIdx.x;
    size_t s0 = (size_t)g_slot[2 * t];
    size_t s1 = (size_t)g_slot[2 * t + 1];
    float* o = out + (size_t)t * DD;
    const float* z0 = g_z + s0 * DD;
    const float* z1 = g_z + s1 * DD;
    for (int d = threadIdx.x; d < DD; d += blockDim.x)
        o[d] += z0[d] + z1[d];
}

// ---------------- HMMA GEMM: C = A @ B^T over K=2048, fp16x2 compensated ----
// CTA tile 128x128, 8 warps (2x4), warp tile 64x32, BK=64, 3-stage cp.async.
// Two K-phases: A_hi @ B, then A_lo @ B (same fp32 accumulator).
// IS13: B rows interleave w1(even)/w3(odd) -> each thread's (d0,d1) = (y0,y1)
// of one act column -> fused gate+SwiGLU, act stored as fp16 hi/lo.
template<bool IS13, bool GATHER>
__global__ void __launch_bounds__(256, 2) moe_gemm(
    const __half* __restrict__ a_hi, const __half* __restrict__ a_lo,
    const __half* __restrict__ b,
    __half* __restrict__ out_hi, __half* __restrict__ out_lo,
    float* __restrict__ out_f,
    int Mfull, const int* __restrict__ counts,
    const int* __restrict__ tok, const float* __restrict__ gate,
    size_t b_estride, int acap, int ccap)
{
    extern __shared__ char smem[];
    const int e   = blockIdx.z;
    const int cnt = counts ? counts[e] : Mfull;
    const int m0  = blockIdx.y * 128;
    if (m0 >= cnt) return;
    const int tid = threadIdx.x;
    const int lane = tid & 31, wid = tid >> 5;

    int*   tok_s  = (int*)smem;
    float* gate_s = (float*)(smem + 512);
    if (GATHER && tid < 128) {
        int r = m0 + tid;
        tok_s[tid]  = (r < cnt) ? tok[e * CAP + r]  : 0;
        gate_s[tid] = (r < cnt) ? gate[e * CAP + r] : 0.f;
    }
    __syncthreads();

    const uint32_t sb = smem_u32(smem) + SM_STAGES;

    // ---- cp.async addressing: thread -> row = tid/2, half-row 64B = tid&1
    const int lr   = tid >> 1;
    const int half = tid & 1;
    size_t aRow;
    if (GATHER) aRow = (size_t)tok_s[lr];
    else        aRow = (size_t)e * (size_t)acap + (size_t)(m0 + lr);
    const char* pAhi = (const char*)(a_hi + aRow * 2048);
    const char* pAlo = (const char*)(a_lo + aRow * 2048);
    size_t bRow;
    if (IS13) bRow = (size_t)((lr & 1) * 2048 + blockIdx.x * 64 + (lr >> 1));
    else      bRow = (size_t)(blockIdx.x * 128 + lr);
    const char* pB = (const char*)(b + (size_t)e * b_estride + bRow * 2048);

    // smem write offsets (XOR swizzle on 16B chunks within 128B rows)
    uint32_t wA[4], wB[4];
#pragma unroll
    for (int j = 0; j < 4; j++) {
        int ch = half * 4 + j;
        wA[j] = (uint32_t)(lr * 128 + ((ch ^ (lr & 7)) << 4));
        wB[j] = (uint32_t)(16384 + lr * 128 + ((ch ^ (lr & 7)) << 4));
    }
    const int gofs = half * 64;   // byte offset within 128B k-chunk

    // ---- ldmatrix lane addressing ----
    const int mw = wid >> 2, nw = wid & 3;
    uint32_t abase[4], axor[4], bbase[4], bxor[4];
#pragma unroll
    for (int mi = 0; mi < 4; mi++) {
        int ar = mw * 64 + mi * 16 + (lane & 15);
        abase[mi] = (uint32_t)(ar * 128);
        axor[mi]  = (uint32_t)(ar & 7);
    }
#pragma unroll
    for (int nj = 0; nj < 4; nj++) {
        int br = nw * 32 + nj * 8 + (lane & 7);
        bbase[nj] = (uint32_t)(16384 + br * 128);
        bxor[nj]  = (uint32_t)(br & 7);
    }
    const uint32_t ahalf = (uint32_t)(lane >> 4);
    const uint32_t bhalf = (uint32_t)((lane >> 3) & 1);

    float acc[4][4][4];
#pragma unroll
    for (int mi = 0; mi < 4; mi++)
#pragma unroll
        for (int nj = 0; nj < 4; nj++)
#pragma unroll
            for (int q = 0; q < 4; q++) acc[mi][nj][q] = 0.f;

    // iteration c in [0,64): phase = c/32 (A_hi, A_lo), k-chunk 128B = (c%32)
    auto issue = [&](int c) {
        const uint32_t st = sb + (c % 3) * STAGE_SZ;
        const char* pa = (c < 32) ? pAhi : pAlo;
        const int kb = (c & 31) * 128 + gofs;
#pragma unroll
        for (int j = 0; j < 4; j++) {
            CPA16(st + wA[j], pa + kb + j * 16);
            CPA16(st + wB[j], pB + kb + j * 16);
        }
        CPA_COMMIT();
    };

    issue(0);
    issue(1);

    for (int c = 0; c < 64; c++) {
        CPA_WAIT1();          // stage c complete (my copies)
        __syncthreads();      // all copies visible; all warps done with iter c-1
        if (c + 2 < 64) issue(c + 2);   // overwrites slot (c-1)%3 — safe now
        const uint32_t st = sb + (c % 3) * STAGE_SZ;
#pragma unroll
        for (int ks = 0; ks < 4; ks++) {
            uint32_t a[4][4], bfr[4][2];
#pragma unroll
            for (int mi = 0; mi < 4; mi++)
                LDSM4(a[mi][0], a[mi][1], a[mi][2], a[mi][3],
                      st + abase[mi] + ((((uint32_t)ks * 2 + ahalf) ^ axor[mi]) << 4));
#pragma unroll
            for (int nj = 0; nj < 4; nj++)
                LDSM2(bfr[nj][0], bfr[nj][1],
                      st + bbase[nj] + ((((uint32_t)ks * 2 + bhalf) ^ bxor[nj]) << 4));
#pragma unroll
            for (int mi = 0; mi < 4; mi++)
#pragma unroll
                for (int nj = 0; nj < 4; nj++)
                    MMA16816(acc[mi][nj], a[mi], bfr[nj]);
        }
    }

    // ---- epilogue ----
#pragma unroll
    for (int mi = 0; mi < 4; mi++) {
        const int lr0 = mw * 64 + mi * 16 + (lane >> 2);
        const int lr1 = lr0 + 8;
        const int r0 = m0 + lr0, r1 = m0 + lr1;
        float g0 = 1.f, g1 = 1.f;
        if (IS13 && GATHER) { g0 = gate_s[lr0]; g1 = gate_s[lr1]; }
#pragma unroll
        for (int nj = 0; nj < 4; nj++) {
            if (IS13) {
                const int actcol = blockIdx.x * 64 + nw * 16 + nj * 4 + (lane & 3);
                if (r0 < cnt) {
                    float y0 = g0 * acc[mi][nj][0], y1 = g0 * acc[mi][nj][1];
                    float v  = y0 / (1.f + expf(-y0)) * y1;
                    __half h = __float2half(v);
                    size_t o = ((size_t)e * ccap + r0) * 2048 + actcol;
                    out_hi[o] = h;
                    out_lo[o] = __float2half(v - __half2float(h));
                }
                if (r1 < cnt) {
                    float y0 = g1 * acc[mi][nj][2], y1 = g1 * acc[mi][nj][3];
                    float v  = y0 / (1.f + expf(-y0)) * y1;
                    __half h = __float2half(v);
                    size_t o = ((size_t)e * ccap + r1) * 2048 + actcol;
                    out_hi[o] = h;
                    out_lo[o] = __float2half(v - __half2float(h));
                }
            } else {
                const int col = blockIdx.x * 128 + nw * 32 + nj * 8 + (lane & 3) * 2;
                if (r0 < cnt)
                    *(float2*)(out_f + ((size_t)e * ccap + r0) * 2048 + col) =
                        make_float2(acc[mi][nj][0], acc[mi][nj][1]);
                if (r1 < cnt)
                    *(float2*)(out_f + ((size_t)e * ccap + r1) * 2048 + col) =
                        make_float2(acc[mi][nj][2], acc[mi][nj][3]);
            }
        }
    }
}

// ---------------- launch ----------------
extern "C" void kernel_launch(void* const* d_in, const int* in_sizes, int n_in,
                              void* d_out, int out_size)
{
    const float* x    = (const float*)d_in[0];
    const float* rte  = (const float*)d_in[1];
    const float* sw13 = (const float*)d_in[2];
    const float* sw2  = (const float*)d_in[3];
    const float* rw13 = (const float*)d_in[4];
    const float* rw2  = (const float*)d_in[5];
    float* out = (float*)d_out;

    __half *xh, *xl, *s13, *s2, *r13, *r2, *ash, *asl, *arh, *arl;
    float *z, *gates;
    int *cnts, *toks;
    cudaGetSymbolAddress((void**)&xh, g_x_hi);
    cudaGetSymbolAddress((void**)&xl, g_x_lo);
    cudaGetSymbolAddress((void**)&s13, g_sw13);
    cudaGetSymbolAddress((void**)&s2, g_sw2);
    cudaGetSymbolAddress((void**)&r13, g_rw13);
    cudaGetSymbolAddress((void**)&r2, g_rw2);
    cudaGetSymbolAddress((void**)&ash, g_actsh_hi);
    cudaGetSymbolAddress((void**)&asl, g_actsh_lo);
    cudaGetSymbolAddress((void**)&arh, g_actrt_hi);
    cudaGetSymbolAddress((void**)&arl, g_actrt_lo);
    cudaGetSymbolAddress((void**)&z, g_z);
    cudaGetSymbolAddress((void**)&cnts, g_counts);
    cudaGetSymbolAddress((void**)&toks, g_tok);
    cudaGetSymbolAddress((void**)&gates, g_gate);

    cudaFuncSetAttribute((const void*)moe_gemm<true,  false>,
                         cudaFuncAttributeMaxDynamicSharedMemorySize, SMEM_BYTES);
    cudaFuncSetAttribute((const void*)moe_gemm<true,  true>,
                         cudaFuncAttributeMaxDynamicSharedMemorySize, SMEM_BYTES);
    cudaFuncSetAttribute((const void*)moe_gemm<false, false>,
                         cudaFuncAttributeMaxDynamicSharedMemorySize, SMEM_BYTES);

    // 1) conversions (one launch)
    {
        ConvArgs ca;
        ca.src[0] = (const float4*)x;    ca.hi[0] = (__half2*)xh;  ca.lo[0] = (__half2*)xl;
        ca.n4[0]  = TT * DD / 4;
        ca.src[1] = (const float4*)sw13; ca.hi[1] = (__half2*)s13; ca.lo[1] = nullptr;
        ca.n4[1]  = 2 * FF * DD / 4;
        ca.src[2] = (const float4*)sw2;  ca.hi[2] = (__half2*)s2;  ca.lo[2] = nullptr;
        ca.n4[2]  = DD * FF / 4;
        ca.src[3] = (const float4*)rw13; ca.hi[3] = (__half2*)r13; ca.lo[3] = nullptr;
        ca.n4[3]  = EE * 2 * FF * DD / 4;
        ca.src[4] = (const float4*)rw2;  ca.hi[4] = (__half2*)r2;  ca.lo[4] = nullptr;
        ca.n4[4]  = EE * DD * FF / 4;
        int total4 = ca.n4[0] + ca.n4[1] + ca.n4[2] + ca.n4[3] + ca.n4[4];
        conv_kernel<<<(total4 + 255) / 256, 256>>>(ca, total4);
    }

    // 2) init, 3) router
    init_kernel<<<1, 32>>>();
    router_kernel<<<TT / 8, 256>>>(x, rte);

    // 4) shared GEMM13 (fused swiglu -> act_sh)
    moe_gemm<true, false><<<dim3(FF / 64, TT / 128, 1), 256, SMEM_BYTES>>>(
        xh, xl, s13, ash, asl, nullptr,
        TT, nullptr, nullptr, nullptr, 0, TT, TT);

    // 5) routed GEMM13 (gathered + gated -> act_rt)
    moe_gemm<true, true><<<dim3(FF / 64, CAP / 128, EE), 256, SMEM_BYTES>>>(
        xh, xl, r13, arh, arl, nullptr,
        CAP, cnts, toks, gates, (size_t)2 * FF * DD, 0, CAP);

    // 6) shared GEMM2 -> out (fp32, full overwrite)   [ncu capture target]
    moe_gemm<false, false><<<dim3(DD / 128, TT / 128, 1), 256, SMEM_BYTES>>>(
        ash, asl, s2, nullptr, nullptr, out,
        TT, nullptr, nullptr, nullptr, 0, TT, TT);

    // 7) routed GEMM2 -> z
    moe_gemm<false, false><<<dim3(DD / 128, CAP / 128, EE), 256, SMEM_BYTES>>>(
        arh, arl, r2, nullptr, nullptr, z,
        CAP, cnts, nullptr, nullptr, (size_t)DD * FF, CAP, CAP);

    // 8) combine
    final_add_kernel<<<TT, 256>>>(out);
}